// round 16
// baseline (speedup 1.0000x reference)
#include <cuda_runtime.h>
#include <cuda_bf16.h>
#include <math.h>
#include <stdint.h>

// SpikeToCalciumDoubleExp: out[b,t] = sum_{j=0}^{K-1} kernel[j] * u[b, t+K-1-j]
// kernel[j] = (g1^{j+1} - g2^{j+1})/scale, g = exp(-1/tau), tau1=20, tau2=2, K=121.
//
// Scaled-state recursion (exact): S = sum_{r=0}^{120} g1^{120-r} u[j+r]
//   S(j+1) = g1*S(j) + u[j+121] - g1^121 * u[j]
//   T(j+1) = g2*T(j) + u[j+121]             (g2^121 ~ 0)
//   out(j) = (g1/scale)*S - (g2/scale)*T
// Seed decomposition for LPT=13 (121 = 9*13 + 4): each thread publishes, over
// its own 13-sample chunk x[]: M13/M4 (g1 Horner + 4-tap snapshot), G13/G4
// (g2). Thread i:  U = ((M_i*g1^13 + M_{i+1})*... + M_{i+8})*g1^4 + M4_{i+9}
// (exact);  QU = (G13_{i+7}*g2^13 + G13_{i+8})*g2^4 + G4_{i+9}  (30-tap g2
// support, dropped weight ~3e-7). 2 chunks per block, double-buffered cp.async.
// Full-window load and full-chunk store loops are compile-time unrolled
// (predicated) — runtime-bound loops only on the boundary chunk.
// Stride-13 (odd) per-lane smem access: bank-conflict-free.

#define THREADS 256
#define LPT 13                       // outputs per thread (odd: conflict-free)
#define CHUNK (THREADS * LPT)        // 3328 outputs per chunk
#define WIN (CHUNK + 128)            // input window incl. K-1 lookahead
#define NM (THREADS + 9)             // Horner tables incl. 9 overhang chunks
#define NCPB 2                       // chunks per block (double buffer)
#define NV_WIN (WIN / 4)             // 864 float4 vectors per window
#define NV_CHUNK (CHUNK / 4)         // 832 float4 vectors per chunk

__device__ __forceinline__ void cp_async16(uint32_t saddr, const float* gptr) {
    asm volatile("cp.async.cg.shared.global [%0], [%1], 16;\n"
                 :: "r"(saddr), "l"(gptr));
}
__device__ __forceinline__ void cp_commit() {
    asm volatile("cp.async.commit_group;\n");
}
template<int N> __device__ __forceinline__ void cp_wait() {
    asm volatile("cp.async.wait_group %0;\n" :: "n"(N));
}

// ---------------- pipelined K=121 fast path ----------------
__global__ void __launch_bounds__(THREADS, 6)
spike2calcium_pipe(const float* __restrict__ u, float* __restrict__ out,
                   int T_out, int in_w) {
    extern __shared__ float dynsm[];          // NCPB buffers of WIN floats
    __shared__ float Msm[NM], M4sm[NM], Gsm[NM], G4sm[NM];

    const int tid = threadIdx.x;
    const int b   = blockIdx.y;
    const int c0  = blockIdx.x * NCPB;        // first global chunk index

    // ---- filter constants ----
    const float tau1 = 20.0f, tau2 = 2.0f;
    const float rr = tau1 / tau2, dd = tau1 - tau2;
    const float scale = powf(rr, -tau2 / dd) - powf(rr, -tau1 / dd);
    const float inv_scale = 1.0f / scale;
    const float g1 = expf(-1.0f / tau1);
    const float g2 = expf(-1.0f / tau2);
    const float cn1 = g1 * inv_scale;
    const float cn2 = g2 * inv_scale;
    const float e121 = expf(-121.0f / tau1);  // g1^121
    const float p13 = expf(-13.0f / tau1);    // g1^13
    const float p4  = expf(-4.0f  / tau1);    // g1^4
    const float q13 = expf(-13.0f / tau2);    // g2^13
    const float q4  = expf(-4.0f  / tau2);    // g2^4

    const float* rowbase = u + (size_t)b * in_w;

    // ---- issue BOTH chunk loads up-front (fire-and-forget) ----
    #pragma unroll
    for (int c = 0; c < NCPB; ++c) {
        const int t0 = (c0 + c) * CHUNK;
        if (t0 < T_out) {
            float* buf = dynsm + c * WIN;
            const int wlen = min(WIN, in_w - t0);
            const float* gp = rowbase + t0;
            uint32_t sb = (uint32_t)__cvta_generic_to_shared(buf);
            if ((((uintptr_t)gp & 15u) == 0) && wlen == WIN) {
                // full window: compile-time trips, predicated last pass
                #pragma unroll
                for (int it = 0; it < (NV_WIN + THREADS - 1) / THREADS; ++it) {
                    int v = tid + it * THREADS;
                    if (v < NV_WIN) cp_async16(sb + (v << 4), gp + (v << 2));
                }
            } else if (((uintptr_t)gp & 15u) == 0) {
                const int nv = wlen >> 2;
                for (int v = tid; v < nv; v += THREADS)
                    cp_async16(sb + (v << 4), gp + (v << 2));
                for (int j = (nv << 2) + tid; j < wlen; j += THREADS)
                    buf[j] = gp[j];
            } else {
                for (int j = tid; j < wlen; j += THREADS)
                    buf[j] = gp[j];
            }
        }
        cp_commit();                           // keep group count fixed
    }

    // ---- process chunks ----
    #pragma unroll
    for (int c = 0; c < NCPB; ++c) {
        const int t0 = (c0 + c) * CHUNK;
        if (t0 >= T_out) break;                // uniform across block
        float* sm = dynsm + c * WIN;

        if (c == 0) cp_wait<NCPB - 1>(); else cp_wait<0>();
        __syncthreads();                       // window c resident

        const int base = tid * LPT;
        int nout = T_out - t0 - base;
        nout = min(nout, LPT);

        // phase 2: own-chunk Horners over register array x[]
        float x[LPT];
        float M = 0.0f, G = 0.0f, M4s = 0.0f, G4s = 0.0f;
        #pragma unroll
        for (int r = 0; r < LPT; ++r) {
            x[r] = sm[base + r];
            M = fmaf(M, g1, x[r]);
            G = fmaf(G, g2, x[r]);
            if (r == 3) { M4s = M; G4s = G; }
        }
        Msm[tid]  = M;
        M4sm[tid] = M4s;
        Gsm[tid]  = G;
        G4sm[tid] = G4s;
        if (tid < 9) {                         // overhang chunks 256..264
            float Mo = 0.0f, Go = 0.0f, M4o = 0.0f, G4o = 0.0f;
            const int ob = CHUNK + tid * LPT;
            #pragma unroll
            for (int r = 0; r < LPT; ++r) {
                float v = sm[ob + r];
                Mo = fmaf(Mo, g1, v);
                Go = fmaf(Go, g2, v);
                if (r == 3) { M4o = Mo; G4o = Go; }
            }
            Msm[THREADS + tid]  = Mo;
            M4sm[THREADS + tid] = M4o;
            Gsm[THREADS + tid]  = Go;
            G4sm[THREADS + tid] = G4o;
        }
        __syncthreads();                       // tables ready

        float o0 = 0.0f;
        if (nout > 0) {
            // g1 seed: Horner over 9 chunk-Horners + 4-tap tail (exact)
            float S = M;
            #pragma unroll
            for (int k = 1; k <= 8; ++k)
                S = fmaf(S, p13, Msm[tid + k]);
            S = fmaf(S, p4, M4sm[tid + 9]);
            // g2 seed: last 30 taps (2 chunks + 4-tap tail)
            float T = fmaf(Gsm[tid + 7], q13, Gsm[tid + 8]);
            T = fmaf(T, q4, G4sm[tid + 9]);
            o0 = fmaf(cn1, S, -(cn2 * T));

            #pragma unroll
            for (int t = 1; t < LPT; ++t) {
                float xn = sm[base + t + 120];
                float xo = x[t - 1];               // register, no LDS
                S = fmaf(g1, S, fmaf(-e121, xo, xn));
                T = fmaf(g2, T, xn);               // g2^121 ~ 0: dropped
                x[t - 1] = fmaf(cn1, S, -(cn2 * T));   // o[t] reuses x[t-1]
            }
        }

        __syncthreads();                       // all reads of window c done
        if (nout > 0) {                        // restage outputs into buffer c
            sm[base] = o0;
            #pragma unroll
            for (int t = 1; t < LPT; ++t)
                if (t < nout) sm[base + t] = x[t - 1];
        }
        __syncthreads();

        const int olen = min(CHUNK, T_out - t0);
        float* orow = out + (size_t)b * T_out + t0;
        if (olen == CHUNK) {
            // full chunk: compile-time trips, predicated last pass
            #pragma unroll
            for (int it = 0; it < (NV_CHUNK + THREADS - 1) / THREADS; ++it) {
                int v = tid + it * THREADS;
                if (v < NV_CHUNK)
                    *(float4*)(orow + (v << 2)) = *(const float4*)&sm[v << 2];
            }
        } else {
            const int nov = olen >> 2;
            for (int v = tid; v < nov; v += THREADS)
                *(float4*)(orow + (v << 2)) = *(const float4*)&sm[v << 2];
            for (int j = (nov << 2) + tid; j < olen; j += THREADS)
                orow[j] = sm[j];
        }
        // next chunk uses the other buffer; table WAR fenced by barriers above.
    }
}

// ---------------- generic runtime-K fallback ----------------
#define GLPT 31
#define GCHUNK (THREADS * GLPT)
#define GWIN (GCHUNK + 128)

__global__ void __launch_bounds__(THREADS, 5)
spike2calcium_generic(const float* __restrict__ u, float* __restrict__ out,
                      int K, int T_out, int in_w) {
    __shared__ float sm[GWIN];
    const int tid = threadIdx.x;
    const int b   = blockIdx.y;
    const int t0  = blockIdx.x * GCHUNK;

    const float tau1 = 20.0f, tau2 = 2.0f;
    const float rr = tau1 / tau2, dd = tau1 - tau2;
    const float scale = powf(rr, -tau2 / dd) - powf(rr, -tau1 / dd);
    const float inv_scale = 1.0f / scale;
    const float g1 = expf(-1.0f / tau1);
    const float g2 = expf(-1.0f / tau2);
    const float cn1 = g1 * inv_scale;
    const float cn2 = g2 * inv_scale;

    const float* row = u + (size_t)b * in_w + t0;
    const int wlen = min(GWIN, in_w - t0);
    const int nv = wlen >> 2;
    const float4* row4 = (const float4*)row;
    for (int v = tid; v < nv; v += THREADS)
        *(float4*)&sm[v << 2] = row4[v];
    for (int j = (nv << 2) + tid; j < wlen; j += THREADS)
        sm[j] = row[j];
    __syncthreads();

    const int base = tid * GLPT;
    int nout = T_out - t0 - base;
    nout = min(nout, GLPT);

    float o[GLPT];
    if (nout > 0) {
        float H1 = 0.0f, H2 = 0.0f;
        for (int r = 0; r < K; ++r) {
            float v = sm[base + r];
            H1 = fmaf(H1, g1, v);
            H2 = fmaf(H2, g2, v);
        }
        float P = H1 * cn1;
        float Q = H2 * cn2;
        o[0] = P - Q;
        const float co1 = expf(-(float)(K + 1) / tau1) * inv_scale;
        const float co2 = expf(-(float)(K + 1) / tau2) * inv_scale;
        #pragma unroll 8
        for (int t = 1; t < GLPT; ++t) {
            float xn = sm[base + t + K - 1];
            float xo = sm[base + t - 1];
            P = fmaf(g1, P, fmaf(cn1, xn, -co1 * xo));
            Q = fmaf(g2, Q, fmaf(cn2, xn, -co2 * xo));
            o[t] = P - Q;
        }
    }
    __syncthreads();
    if (nout > 0) {
        #pragma unroll
        for (int t = 0; t < GLPT; ++t)
            if (t < nout) sm[base + t] = o[t];
    }
    __syncthreads();

    const int olen = min(GCHUNK, T_out - t0);
    float* orow = out + (size_t)b * T_out + t0;
    const int nov = olen >> 2;
    for (int v = tid; v < nov; v += THREADS)
        *(float4*)(orow + (v << 2)) = *(const float4*)&sm[v << 2];
    for (int j = (nov << 2) + tid; j < olen; j += THREADS)
        orow[j] = sm[j];
}

extern "C" void kernel_launch(void* const* d_in, const int* in_sizes, int n_in,
                              void* d_out, int out_size) {
    const float* u = (const float*)d_in[0];
    const int K = in_sizes[1];                              // 121
    const int rows  = (in_sizes[0] - out_size) / (K - 1);   // 1024
    const int T_out = out_size / rows;                      // 30000
    const int in_w  = T_out + K - 1;                        // 30120

    if (K == 121) {
        const int n_chunks = (T_out + CHUNK - 1) / CHUNK;   // 10
        const int bx = (n_chunks + NCPB - 1) / NCPB;        // 5
        const int dsmem = NCPB * WIN * (int)sizeof(float);  // 27648 B
        cudaFuncSetAttribute(spike2calcium_pipe,
                             cudaFuncAttributeMaxDynamicSharedMemorySize, dsmem);
        dim3 grid(bx, rows);
        spike2calcium_pipe<<<grid, THREADS, dsmem>>>(u, (float*)d_out, T_out, in_w);
    } else {
        const int n_chunks = (T_out + GCHUNK - 1) / GCHUNK;
        dim3 grid(n_chunks, rows);
        spike2calcium_generic<<<grid, THREADS>>>(u, (float*)d_out, K, T_out, in_w);
    }
}